// round 10
// baseline (speedup 1.0000x reference)
#include <cuda_runtime.h>

#define BB 32
#define LL 4096
#define CC 7
#define NK 74
#define TL 64
#define SX 92           // multiple of 4 floats (16B rows); >= 88 staged entries
#define NCOL 512

typedef unsigned long long u64;

__device__ __forceinline__ u64 fma2(u64 a, u64 b, u64 c) {
    u64 d;
    asm("fma.rn.f32x2 %0, %1, %2, %3;" : "=l"(d) : "l"(a), "l"(b), "l"(c));
    return d;
}

__device__ __forceinline__ u64 pack2(float lo, float hi) {
    u64 d;
    asm("mov.b64 %0, {%1, %2};" : "=l"(d) : "f"(lo), "f"(hi));
    return d;
}

__device__ __forceinline__ void unpack2(u64 v, float& lo, float& hi) {
    asm("mov.b64 {%0, %1}, %2;" : "=f"(lo), "=f"(hi) : "l"(v));
}

// Accumulate pair P into all outputs d = P-2j, j in [0,12), d in [0,8).
__device__ __forceinline__ void feed(int P, u64 pr, const u64* __restrict__ Wp,
                                     u64 acc[8]) {
    #pragma unroll
    for (int d = 0; d < 8; d++) {
        if (((P - d) & 1) == 0) {
            const int j = (P - d) >> 1;
            if (j >= 0 && j < 12) acc[d] = fma2(Wp[j], pr, acc[d]);
        }
    }
}

__global__ __launch_bounds__(NCOL, 2)
void rocket_conv_kernel(const float* __restrict__ x,
                        const float* __restrict__ kern,
                        float* __restrict__ out) {
    __shared__ __align__(16) float xs[CC][SX];   // xhat[t] = x[b, l0-22+t]

    const int b   = blockIdx.y;
    const int l0  = blockIdx.x * TL;
    const int tid = threadIdx.x;

    // ---- stage x window, zero-extended, t in [0, 88) ----
    const int NLOAD = 88 * CC;
    for (int i = tid; i < NLOAD; i += NCOL) {
        int t = i / CC, c = i % CC;
        int g = l0 - 22 + t;
        xs[c][t] = (g >= 0 && g < LL) ? x[(b * LL + g) * CC + c] : 0.0f;
    }

    // ---- per-thread column mapping ----
    const int col = tid;
    const int c = (col < 511) ? (col / 73) : 0;
    const int k = (col < 511) ? (col % 73) : 73;

    // Dense 24-tap filter, tap m (time offset m-22):
    //   Wm[m] = kernels[k, 7 - m/3, m%3] -> flat k*24 + 21 - 3*(m/3) + m%3
    // Load the thread's 24 weights straight from global (L2-resident),
    // packed as adjacent-tap pairs Wp[j] = (Wm[2j], Wm[2j+1]).
    const float* kr = kern + k * 24;
    u64 Wp[12];
    #pragma unroll
    for (int j = 0; j < 12; j++) {
        int me = 2 * j, mo = 2 * j + 1;
        float we = __ldg(kr + 21 - 3 * (me / 3) + (me % 3));
        float wo = __ldg(kr + 21 - 3 * (mo / 3) + (mo % 3));
        Wp[j] = pack2(we, wo);
    }

    __syncthreads();

    const float* rowA = xs[c];
    float* outp = out + ((size_t)(b * LL + l0)) * NCOL + col;

    #pragma unroll 1
    for (int lt = 0; lt < TL; lt += 8) {
        u64 acc[8];
        #pragma unroll
        for (int d = 0; d < 8; d++) acc[d] = 0ull;

        const float* base = rowA + lt;
        float4 cur = *reinterpret_cast<const float4*>(base);
        // chunk i holds xhat[lt+4i .. lt+4i+3]; pair P = (v[P], v[P+1]).
        #pragma unroll
        for (int i = 0; i < 8; i++) {
            float4 nxt;
            if (i < 7) nxt = *reinterpret_cast<const float4*>(base + 4 * i + 4);
            feed(4 * i + 0, pack2(cur.x, cur.y), Wp, acc);
            feed(4 * i + 1, pack2(cur.y, cur.z), Wp, acc);
            feed(4 * i + 2, pack2(cur.z, cur.w), Wp, acc);
            if (i < 7) {
                feed(4 * i + 3, pack2(cur.w, nxt.x), Wp, acc);
                cur = nxt;
            }
        }

        #pragma unroll
        for (int d = 0; d < 8; d++) {
            float lo, hi;
            unpack2(acc[d], lo, hi);
            outp[(size_t)d * NCOL] = lo + hi;
        }
        outp += (size_t)8 * NCOL;
    }

    // ---- fix l = L-1: reference zero-pads the whole win row at t=L, so ALL
    // j=2 taps vanish there (not plain x zero-extension). Recompute with
    // j in {0,1} only, extracting scalar weights from the packed regs:
    // W[i][j] lives at tap m = 21 - 3i + j -> lane (m&1) of Wp[m>>1].
    if (l0 + TL == LL) {
        float s = 0.0f;
        #pragma unroll
        for (int i = 0; i < 8; i++) {
            #pragma unroll
            for (int j = 0; j < 2; j++) {
                const int m = 21 - 3 * i + j;
                float lo, hi;
                unpack2(Wp[m >> 1], lo, hi);
                float w = (m & 1) ? hi : lo;
                s += w * rowA[TL + 20 + j - 3 * i];   // xhat[L-2+j-3i], always staged
            }
        }
        out[((size_t)(b * LL + LL - 1)) * NCOL + col] = s;
    }
}

extern "C" void kernel_launch(void* const* d_in, const int* in_sizes, int n_in,
                              void* d_out, int out_size) {
    const float* x    = (const float*)d_in[0];
    const float* kern = (const float*)d_in[1];
    float* out        = (float*)d_out;
    dim3 grid(LL / TL, BB);
    rocket_conv_kernel<<<grid, NCOL>>>(x, kern, out);
}

// round 11
// speedup vs baseline: 1.2167x; 1.2167x over previous
#include <cuda_runtime.h>

#define BB 32
#define LL 4096
#define CC 7
#define NK 74
#define TL 64
#define SX 92           // multiple of 4 floats -> every row 16B aligned; >= 88 staged
#define NCOL 512

typedef unsigned long long u64;

__device__ __forceinline__ u64 fma2(u64 a, u64 b, u64 c) {
    u64 d;
    asm("fma.rn.f32x2 %0, %1, %2, %3;" : "=l"(d) : "l"(a), "l"(b), "l"(c));
    return d;
}

__device__ __forceinline__ u64 pack2(float lo, float hi) {
    u64 d;
    asm("mov.b64 %0, {%1, %2};" : "=l"(d) : "f"(lo), "f"(hi));
    return d;
}

__device__ __forceinline__ void unpack2(u64 v, float& lo, float& hi) {
    asm("mov.b64 {%0, %1}, %2;" : "=f"(lo), "=f"(hi) : "l"(v));
}

// One pass: 4 outputs at even local offsets {0,2,4,6} relative to `base`'s
// pair indexing. Pair P = (base[2P], base[2P+1]); chunk i (16B) = pairs 2i, 2i+1.
// Output t accumulates fma2(W[j], pair(t+j)) for j in [0,12).
__device__ __forceinline__ void pass_quad(const float* __restrict__ base,
                                          const u64* __restrict__ W,  // 12 tap-pairs
                                          u64 acc[4]) {
    #pragma unroll
    for (int i = 0; i < 8; i++) {
        ulonglong2 ch = *reinterpret_cast<const ulonglong2*>(base + 4 * i);
        #pragma unroll
        for (int h = 0; h < 2; h++) {
            const int P = 2 * i + h;
            u64 pr = h ? ch.y : ch.x;
            #pragma unroll
            for (int t = 0; t < 4; t++) {
                const int j = P - t;
                if (j >= 0 && j < 12) acc[t] = fma2(W[j], pr, acc[t]);
            }
        }
    }
}

__global__ __launch_bounds__(NCOL, 2)
void rocket_conv_kernel(const float* __restrict__ x,
                        const float* __restrict__ kern,
                        float* __restrict__ out) {
    __shared__ __align__(16) float xsA[CC][SX];   // xhat[t]   (even-offset pairs)
    __shared__ __align__(16) float xsB[CC][SX];   // xhat[t+1] (odd-offset pairs)

    const int b   = blockIdx.y;
    const int l0  = blockIdx.x * TL;
    const int tid = threadIdx.x;

    // ---- stage x window xhat[t] = x[b, l0-22+t], zero-extended, t in [0,88) ----
    const int NLOAD = 88 * CC;
    for (int i = tid; i < NLOAD; i += NCOL) {
        int t = i / CC, c = i % CC;
        int g = l0 - 22 + t;
        float v = (g >= 0 && g < LL) ? x[(b * LL + g) * CC + c] : 0.0f;
        xsA[c][t] = v;
        if (t >= 1) xsB[c][t - 1] = v;
    }

    // ---- per-thread column mapping ----
    const int col = tid;
    const int c = (col < 511) ? (col / 73) : 0;
    const int k = (col < 511) ? (col % 73) : 73;

    // Dense 24-tap filter, tap m (time offset m-22):
    //   Wm[m] = kernels[k, 7 - m/3, m%3] -> flat k*24 + 21 - 3*(m/3) + m%3
    // Loaded straight from global (L2-resident), packed as adjacent-tap pairs
    // Wp[j] = (Wm[2j], Wm[2j+1]).
    const float* kr = kern + k * 24;
    u64 Wp[12];
    #pragma unroll
    for (int j = 0; j < 12; j++) {
        int me = 2 * j, mo = 2 * j + 1;
        float we = __ldg(kr + 21 - 3 * (me / 3) + (me % 3));
        float wo = __ldg(kr + 21 - 3 * (mo / 3) + (mo % 3));
        Wp[j] = pack2(we, wo);
    }

    __syncthreads();

    const float* rowA = xsA[c];
    const float* rowB = xsB[c];
    float* outp = out + ((size_t)(b * LL + l0)) * NCOL + col;

    #pragma unroll 1
    for (int lt = 0; lt < TL; lt += 8) {
        u64 aE[4] = {0ull, 0ull, 0ull, 0ull};   // outputs lt+0,2,4,6
        u64 aO[4] = {0ull, 0ull, 0ull, 0ull};   // outputs lt+1,3,5,7
        // even offsets d=2t: pairs (xhat[lt+d+2j], xhat[lt+d+2j+1]) from rowA
        pass_quad(rowA + lt, Wp, aE);
        // odd offsets d=2t+1: same pairs shifted by one -> rowB
        pass_quad(rowB + lt, Wp, aO);

        #pragma unroll
        for (int t = 0; t < 4; t++) {
            float lo, hi;
            unpack2(aE[t], lo, hi);
            outp[(size_t)(2 * t) * NCOL] = lo + hi;
            unpack2(aO[t], lo, hi);
            outp[(size_t)(2 * t + 1) * NCOL] = lo + hi;
        }
        outp += (size_t)8 * NCOL;
    }

    // ---- fix l = L-1: reference zero-pads the whole win row at t=L, so ALL
    // j=2 taps vanish there (not plain x zero-extension). Recompute with
    // j in {0,1} only; W[i][j] is tap m = 21 - 3i + j -> lane (m&1) of Wp[m>>1].
    if (l0 + TL == LL) {
        float s = 0.0f;
        #pragma unroll
        for (int i = 0; i < 8; i++) {
            #pragma unroll
            for (int j = 0; j < 2; j++) {
                const int m = 21 - 3 * i + j;
                float lo, hi;
                unpack2(Wp[m >> 1], lo, hi);
                float w = (m & 1) ? hi : lo;
                s += w * rowA[TL + 20 + j - 3 * i];   // xhat[L-2+j-3i], staged
            }
        }
        out[((size_t)(b * LL + LL - 1)) * NCOL + col] = s;
    }
}

extern "C" void kernel_launch(void* const* d_in, const int* in_sizes, int n_in,
                              void* d_out, int out_size) {
    const float* x    = (const float*)d_in[0];
    const float* kern = (const float*)d_in[1];
    float* out        = (float*)d_out;
    dim3 grid(LL / TL, BB);
    rocket_conv_kernel<<<grid, NCOL>>>(x, kern, out);
}

// round 14
// speedup vs baseline: 1.3729x; 1.1283x over previous
#include <cuda_runtime.h>

#define BB 32
#define LL 4096
#define CC 7
#define NK 74
#define TL 64
#define SX 92           // multiple of 4 floats -> every row 16B aligned; >= 88 staged
#define NCOL 512

typedef unsigned long long u64;

__device__ __forceinline__ u64 fma2(u64 a, u64 b, u64 c) {
    u64 d;
    asm("fma.rn.f32x2 %0, %1, %2, %3;" : "=l"(d) : "l"(a), "l"(b), "l"(c));
    return d;
}

__device__ __forceinline__ u64 pack2(float lo, float hi) {
    u64 d;
    asm("mov.b64 %0, {%1, %2};" : "=l"(d) : "f"(lo), "f"(hi));
    return d;
}

__device__ __forceinline__ void unpack2(u64 v, float& lo, float& hi) {
    asm("mov.b64 {%0, %1}, %2;" : "=f"(lo), "=f"(hi) : "l"(v));
}

// One pass: 4 outputs at even local offsets {0,2,4,6} relative to `base`'s
// pair indexing. Pair P = (base[2P], base[2P+1]); chunk i (16B) = pairs 2i, 2i+1.
// Output t accumulates fma2(W[j], pair(t+j)) for j in [0,12).
__device__ __forceinline__ void pass_quad(const float* __restrict__ base,
                                          const u64* __restrict__ W,  // 12 tap-pairs
                                          u64 acc[4]) {
    #pragma unroll
    for (int i = 0; i < 8; i++) {
        ulonglong2 ch = *reinterpret_cast<const ulonglong2*>(base + 4 * i);
        #pragma unroll
        for (int h = 0; h < 2; h++) {
            const int P = 2 * i + h;
            u64 pr = h ? ch.y : ch.x;
            #pragma unroll
            for (int t = 0; t < 4; t++) {
                const int j = P - t;
                if (j >= 0 && j < 12) acc[t] = fma2(W[j], pr, acc[t]);
            }
        }
    }
}

__global__ __launch_bounds__(NCOL, 2)
void rocket_conv_kernel(const float* __restrict__ x,
                        const float* __restrict__ kern,
                        float* __restrict__ out) {
    __shared__ __align__(16) float ks[NK * 24];
    __shared__ __align__(16) float xsA[CC][SX];   // xhat[t]   (even-offset pairs)
    __shared__ __align__(16) float xsB[CC][SX];   // xhat[t+1] (odd-offset pairs)

    const int b   = blockIdx.y;
    const int l0  = blockIdx.x * TL;
    const int tid = threadIdx.x;

    // ---- stage kernels (coalesced LDG -> STS; read back via broadcast LDS) ----
    for (int i = tid; i < NK * 24; i += NCOL) ks[i] = kern[i];

    // ---- stage x window xhat[t] = x[b, l0-22+t], zero-extended, t in [0,88) ----
    const int NLOAD = 88 * CC;
    for (int i = tid; i < NLOAD; i += NCOL) {
        int t = i / CC, c = i % CC;
        int g = l0 - 22 + t;
        float v = (g >= 0 && g < LL) ? x[(b * LL + g) * CC + c] : 0.0f;
        xsA[c][t] = v;
        if (t >= 1) xsB[c][t - 1] = v;
    }
    __syncthreads();

    // ---- per-thread column mapping ----
    const int col = tid;
    const int c = (col < 511) ? (col / 73) : 0;
    const int k = (col < 511) ? (col % 73) : 73;

    // Dense 24-tap filter, tap m (time offset m-22):
    //   Wm[m] = kernels[k, 7 - m/3, m%3] -> flat k*24 + 21 - 3*(m/3) + m%3
    // Packed as adjacent-tap pairs: Wp[j] = (Wm[2j], Wm[2j+1]).
    u64 Wp[12];
    #pragma unroll
    for (int j = 0; j < 12; j++) {
        int me = 2 * j, mo = 2 * j + 1;
        float we = ks[k * 24 + 21 - 3 * (me / 3) + (me % 3)];
        float wo = ks[k * 24 + 21 - 3 * (mo / 3) + (mo % 3)];
        Wp[j] = pack2(we, wo);
    }

    const float* rowA = xsA[c];
    const float* rowB = xsB[c];
    float* outp = out + ((size_t)(b * LL + l0)) * NCOL + col;

    #pragma unroll 1
    for (int lt = 0; lt < TL; lt += 8) {
        u64 aE[4] = {0ull, 0ull, 0ull, 0ull};   // outputs lt+0,2,4,6
        u64 aO[4] = {0ull, 0ull, 0ull, 0ull};   // outputs lt+1,3,5,7
        // even offsets d=2t: pairs (xhat[lt+d+2j], xhat[lt+d+2j+1]) from rowA
        pass_quad(rowA + lt, Wp, aE);
        // odd offsets d=2t+1: same pairs shifted by one -> rowB
        pass_quad(rowB + lt, Wp, aO);

        #pragma unroll
        for (int t = 0; t < 4; t++) {
            float lo, hi;
            unpack2(aE[t], lo, hi);
            outp[(size_t)(2 * t) * NCOL] = lo + hi;
            unpack2(aO[t], lo, hi);
            outp[(size_t)(2 * t + 1) * NCOL] = lo + hi;
        }
        outp += (size_t)8 * NCOL;
    }

    // ---- fix l = L-1: reference zero-pads the whole win row at t=L, so ALL
    // j=2 taps vanish there (not plain x zero-extension). Recompute with
    // j in {0,1} only.
    if (l0 + TL == LL) {
        float s = 0.0f;
        #pragma unroll
        for (int i = 0; i < 8; i++) {
            #pragma unroll
            for (int j = 0; j < 2; j++) {
                s += ks[k * 24 + i * 3 + j] * rowA[TL + 20 + j - 3 * i];
            }
        }
        out[((size_t)(b * LL + LL - 1)) * NCOL + col] = s;
    }
}

extern "C" void kernel_launch(void* const* d_in, const int* in_sizes, int n_in,
                              void* d_out, int out_size) {
    const float* x    = (const float*)d_in[0];
    const float* kern = (const float*)d_in[1];
    float* out        = (float*)d_out;
    dim3 grid(LL / TL, BB);
    rocket_conv_kernel<<<grid, NCOL>>>(x, kern, out);
}

// round 15
// speedup vs baseline: 1.3862x; 1.0097x over previous
#include <cuda_runtime.h>

#define BB 32
#define LL 4096
#define CC 7
#define NK 74
#define TL 64
#define SX 92            // row stride, multiple of 4 -> 16B-aligned rows
#define NCOL 512
#define GRID 304         // 2 CTAs x 152 SMs, all co-resident
#define TPB (LL / TL)    // 64 tiles per batch
#define NTILES (BB * TPB)  // 2048
#define NLOAD (88 * CC)  // 616 staged floats per tile

typedef unsigned long long u64;

__device__ __forceinline__ u64 fma2(u64 a, u64 b, u64 c) {
    u64 d;
    asm("fma.rn.f32x2 %0, %1, %2, %3;" : "=l"(d) : "l"(a), "l"(b), "l"(c));
    return d;
}

__device__ __forceinline__ u64 pack2(float lo, float hi) {
    u64 d;
    asm("mov.b64 %0, {%1, %2};" : "=l"(d) : "f"(lo), "f"(hi));
    return d;
}

__device__ __forceinline__ void unpack2(u64 v, float& lo, float& hi) {
    asm("mov.b64 {%0, %1}, %2;" : "=f"(lo), "=f"(hi) : "l"(v));
}

// One pass: 4 outputs at even local offsets {0,2,4,6} in `base`'s pair indexing.
// Pair P = (base[2P], base[2P+1]); chunk i (16B) = pairs 2i, 2i+1.
// Output t accumulates fma2(W[j], pair(t+j)) for j in [0,12).
__device__ __forceinline__ void pass_quad(const float* __restrict__ base,
                                          const u64* __restrict__ W,
                                          u64 acc[4]) {
    #pragma unroll
    for (int i = 0; i < 8; i++) {
        ulonglong2 ch = *reinterpret_cast<const ulonglong2*>(base + 4 * i);
        #pragma unroll
        for (int h = 0; h < 2; h++) {
            const int P = 2 * i + h;
            u64 pr = h ? ch.y : ch.x;
            #pragma unroll
            for (int t = 0; t < 4; t++) {
                const int j = P - t;
                if (j >= 0 && j < 12) acc[t] = fma2(W[j], pr, acc[t]);
            }
        }
    }
}

__global__ __launch_bounds__(NCOL, 2)
void rocket_conv_kernel(const float* __restrict__ x,
                        const float* __restrict__ kern,
                        float* __restrict__ out) {
    __shared__ __align__(16) float ks[NK * 24];
    __shared__ __align__(16) float xsA[2][CC][SX];   // xhat[t]   per buffer
    __shared__ __align__(16) float xsB[2][CC][SX];   // xhat[t+1] per buffer

    const int tid = threadIdx.x;

    // ---- stage kernels once per CTA ----
    for (int i = tid; i < NK * 24; i += NCOL) ks[i] = kern[i];

    // ---- per-thread staging slots (fixed across tiles) ----
    const int i1ok = (tid + NCOL) < NLOAD;           // tid < 104

    // prefetch tile 0 (overlaps the ks barrier latency)
    float v0 = 0.0f, v1 = 0.0f;
    {
        const int tt = blockIdx.x;
        const int b = tt / TPB, l0 = (tt % TPB) * TL;
        int t0 = tid / CC, c0 = tid - t0 * CC;
        int g0 = l0 - 22 + t0;
        if ((unsigned)g0 < LL) v0 = x[(b * LL + g0) * CC + c0];
        if (i1ok) {
            int i1 = tid + NCOL;
            int t1 = i1 / CC, c1 = i1 - t1 * CC;
            int g1 = l0 - 22 + t1;
            if ((unsigned)g1 < LL) v1 = x[(b * LL + g1) * CC + c1];
        }
    }
    __syncthreads();   // ks visible

    // ---- per-thread column mapping + packed weights (once per CTA) ----
    const int col = tid;
    const int c = (col < 511) ? (col / 73) : 0;
    const int k = (col < 511) ? (col % 73) : 73;
    // tap m (time offset m-22): Wm[m] = ks[k*24 + 21 - 3*(m/3) + m%3]
    u64 Wp[12];
    #pragma unroll
    for (int j = 0; j < 12; j++) {
        int me = 2 * j, mo = 2 * j + 1;
        float we = ks[k * 24 + 21 - 3 * (me / 3) + (me % 3)];
        float wo = ks[k * 24 + 21 - 3 * (mo / 3) + (mo % 3)];
        Wp[j] = pack2(we, wo);
    }

    // ---- store tile 0 into buffer 0 ----
    {
        int t0 = tid / CC, c0 = tid - t0 * CC;
        xsA[0][c0][t0] = v0;
        if (t0 >= 1) xsB[0][c0][t0 - 1] = v0;
        if (i1ok) {
            int i1 = tid + NCOL;
            int t1 = i1 / CC, c1 = i1 - t1 * CC;   // t1 >= 73, always >= 1
            xsA[0][c1][t1] = v1;
            xsB[0][c1][t1 - 1] = v1;
        }
    }
    __syncthreads();

    int p = 0;
    #pragma unroll 1
    for (int it = 0;; it++) {
        const int tt = blockIdx.x + it * GRID;
        if (tt >= NTILES) break;
        const int ttn = tt + GRID;
        const bool hasnext = (ttn < NTILES);

        // ---- prefetch next tile into registers (hidden under compute) ----
        float n0 = 0.0f, n1 = 0.0f;
        if (hasnext) {
            const int bn = ttn / TPB, l0n = (ttn % TPB) * TL;
            int t0 = tid / CC, c0 = tid - t0 * CC;
            int g0 = l0n - 22 + t0;
            if ((unsigned)g0 < LL) n0 = x[(bn * LL + g0) * CC + c0];
            if (i1ok) {
                int i1 = tid + NCOL;
                int t1 = i1 / CC, c1 = i1 - t1 * CC;
                int g1 = l0n - 22 + t1;
                if ((unsigned)g1 < LL) n1 = x[(bn * LL + g1) * CC + c1];
            }
        }

        // ---- compute current tile from buffer p ----
        const int b = tt / TPB, l0 = (tt % TPB) * TL;
        const float* rowA = xsA[p][c];
        const float* rowB = xsB[p][c];
        float* outp = out + ((size_t)(b * LL + l0)) * NCOL + col;

        #pragma unroll 1
        for (int lt = 0; lt < TL; lt += 8) {
            u64 aE[4] = {0ull, 0ull, 0ull, 0ull};   // outputs lt+0,2,4,6
            u64 aO[4] = {0ull, 0ull, 0ull, 0ull};   // outputs lt+1,3,5,7
            pass_quad(rowA + lt, Wp, aE);
            pass_quad(rowB + lt, Wp, aO);

            #pragma unroll
            for (int t = 0; t < 4; t++) {
                float lo, hi;
                unpack2(aE[t], lo, hi);
                outp[(size_t)(2 * t) * NCOL] = lo + hi;
                unpack2(aO[t], lo, hi);
                outp[(size_t)(2 * t + 1) * NCOL] = lo + hi;
            }
            outp += (size_t)8 * NCOL;
        }

        // ---- fix l = L-1: reference zero-pads the whole win row at t=L, so
        // ALL j=2 taps vanish there. Recompute with j in {0,1}. ----
        if (l0 + TL == LL) {
            float s = 0.0f;
            #pragma unroll
            for (int i = 0; i < 8; i++) {
                #pragma unroll
                for (int j = 0; j < 2; j++) {
                    s += ks[k * 24 + i * 3 + j] * rowA[TL + 20 + j - 3 * i];
                }
            }
            out[((size_t)(b * LL + LL - 1)) * NCOL + col] = s;
        }

        // ---- publish next tile into the other buffer ----
        if (hasnext) {
            int q = p ^ 1;
            int t0 = tid / CC, c0 = tid - t0 * CC;
            xsA[q][c0][t0] = n0;
            if (t0 >= 1) xsB[q][c0][t0 - 1] = n0;
            if (i1ok) {
                int i1 = tid + NCOL;
                int t1 = i1 / CC, c1 = i1 - t1 * CC;
                xsA[q][c1][t1] = n1;
                xsB[q][c1][t1 - 1] = n1;
            }
            __syncthreads();
            p = q;
        }
    }
}

extern "C" void kernel_launch(void* const* d_in, const int* in_sizes, int n_in,
                              void* d_out, int out_size) {
    const float* x    = (const float*)d_in[0];
    const float* kern = (const float*)d_in[1];
    float* out        = (float*)d_out;
    rocket_conv_kernel<<<GRID, NCOL>>>(x, kern, out);
}

// round 17
// speedup vs baseline: 1.3892x; 1.0021x over previous
#include <cuda_runtime.h>

#define BB 32
#define LL 4096
#define CC 7
#define NK 74
#define TL 64
#define SX 92            // row stride, multiple of 4 -> 16B-aligned rows
#define NCOL 512
#define GRID 304         // 2 CTAs x 152 SMs, all co-resident
#define TPB (LL / TL)    // 64 tiles per batch
#define NTILES (BB * TPB)  // 2048
#define NLOAD (88 * CC)  // 616 staged floats per tile

typedef unsigned long long u64;

__device__ __forceinline__ u64 fma2(u64 a, u64 b, u64 c) {
    u64 d;
    asm("fma.rn.f32x2 %0, %1, %2, %3;" : "=l"(d) : "l"(a), "l"(b), "l"(c));
    return d;
}

__device__ __forceinline__ u64 pack2(float lo, float hi) {
    u64 d;
    asm("mov.b64 %0, {%1, %2};" : "=l"(d) : "f"(lo), "f"(hi));
    return d;
}

__device__ __forceinline__ void unpack2(u64 v, float& lo, float& hi) {
    asm("mov.b64 {%0, %1}, %2;" : "=f"(lo), "=f"(hi) : "l"(v));
}

// One pass: 4 outputs at even local offsets {0,2,4,6} in `base`'s pair indexing.
// Pair P = (base[2P], base[2P+1]); chunk i (16B) = pairs 2i, 2i+1.
// Output t accumulates fma2(W[j], pair(t+j)) for j in [0,12).
__device__ __forceinline__ void pass_quad(const float* __restrict__ base,
                                          const u64* __restrict__ W,
                                          u64 acc[4]) {
    #pragma unroll
    for (int i = 0; i < 8; i++) {
        ulonglong2 ch = *reinterpret_cast<const ulonglong2*>(base + 4 * i);
        #pragma unroll
        for (int h = 0; h < 2; h++) {
            const int P = 2 * i + h;
            u64 pr = h ? ch.y : ch.x;
            #pragma unroll
            for (int t = 0; t < 4; t++) {
                const int j = P - t;
                if (j >= 0 && j < 12) acc[t] = fma2(W[j], pr, acc[t]);
            }
        }
    }
}

__global__ __launch_bounds__(NCOL, 2)
void rocket_conv_kernel(const float* __restrict__ x,
                        const float* __restrict__ kern,
                        float* __restrict__ out) {
    __shared__ __align__(16) float ks[NK * 24];
    __shared__ __align__(16) float xsA[2][CC][SX];   // xhat[t]   per buffer
    __shared__ __align__(16) float xsB[2][CC][SX];   // xhat[t+1] per buffer

    const int tid = threadIdx.x;

    // ---- stage kernels once per CTA ----
    for (int i = tid; i < NK * 24; i += NCOL) ks[i] = kern[i];

    // ---- per-thread staging slots (fixed across tiles) ----
    const int i1ok = (tid + NCOL) < NLOAD;           // tid < 104

    // prefetch tile 0 (overlaps the ks barrier latency)
    float v0 = 0.0f, v1 = 0.0f;
    {
        const int tt = blockIdx.x;
        const int b = tt / TPB, l0 = (tt % TPB) * TL;
        int t0 = tid / CC, c0 = tid - t0 * CC;
        int g0 = l0 - 22 + t0;
        if ((unsigned)g0 < LL) v0 = x[(b * LL + g0) * CC + c0];
        if (i1ok) {
            int i1 = tid + NCOL;
            int t1 = i1 / CC, c1 = i1 - t1 * CC;
            int g1 = l0 - 22 + t1;
            if ((unsigned)g1 < LL) v1 = x[(b * LL + g1) * CC + c1];
        }
    }
    __syncthreads();   // ks visible

    // ---- per-thread column mapping + packed weights (once per CTA) ----
    const int col = tid;
    const int c = (col < 511) ? (col / 73) : 0;
    const int k = (col < 511) ? (col % 73) : 73;
    // tap m (time offset m-22): Wm[m] = ks[k*24 + 21 - 3*(m/3) + m%3]
    u64 Wp[12];
    #pragma unroll
    for (int j = 0; j < 12; j++) {
        int me = 2 * j, mo = 2 * j + 1;
        float we = ks[k * 24 + 21 - 3 * (me / 3) + (me % 3)];
        float wo = ks[k * 24 + 21 - 3 * (mo / 3) + (mo % 3)];
        Wp[j] = pack2(we, wo);
    }

    // ---- store tile 0 into buffer 0 ----
    {
        int t0 = tid / CC, c0 = tid - t0 * CC;
        xsA[0][c0][t0] = v0;
        if (t0 >= 1) xsB[0][c0][t0 - 1] = v0;
        if (i1ok) {
            int i1 = tid + NCOL;
            int t1 = i1 / CC, c1 = i1 - t1 * CC;   // t1 >= 73, always >= 1
            xsA[0][c1][t1] = v1;
            xsB[0][c1][t1 - 1] = v1;
        }
    }
    __syncthreads();

    int p = 0;
    #pragma unroll 1
    for (int it = 0;; it++) {
        const int tt = blockIdx.x + it * GRID;
        if (tt >= NTILES) break;
        const int ttn = tt + GRID;
        const bool hasnext = (ttn < NTILES);

        // ---- prefetch next tile into registers (hidden under compute) ----
        float n0 = 0.0f, n1 = 0.0f;
        if (hasnext) {
            const int bn = ttn / TPB, l0n = (ttn % TPB) * TL;
            int t0 = tid / CC, c0 = tid - t0 * CC;
            int g0 = l0n - 22 + t0;
            if ((unsigned)g0 < LL) n0 = x[(bn * LL + g0) * CC + c0];
            if (i1ok) {
                int i1 = tid + NCOL;
                int t1 = i1 / CC, c1 = i1 - t1 * CC;
                int g1 = l0n - 22 + t1;
                if ((unsigned)g1 < LL) n1 = x[(bn * LL + g1) * CC + c1];
            }
        }

        // ---- compute current tile from buffer p ----
        const int b = tt / TPB, l0 = (tt % TPB) * TL;
        const float* rowA = xsA[p][c];
        const float* rowB = xsB[p][c];
        float* outp = out + ((size_t)(b * LL + l0)) * NCOL + col;

        #pragma unroll 1
        for (int lt = 0; lt < TL; lt += 8) {
            u64 aE[4] = {0ull, 0ull, 0ull, 0ull};   // outputs lt+0,2,4,6
            u64 aO[4] = {0ull, 0ull, 0ull, 0ull};   // outputs lt+1,3,5,7
            pass_quad(rowA + lt, Wp, aE);
            pass_quad(rowB + lt, Wp, aO);

            #pragma unroll
            for (int t = 0; t < 4; t++) {
                float lo, hi;
                unpack2(aE[t], lo, hi);
                outp[(size_t)(2 * t) * NCOL] = lo + hi;
                unpack2(aO[t], lo, hi);
                outp[(size_t)(2 * t + 1) * NCOL] = lo + hi;
            }
            outp += (size_t)8 * NCOL;
        }

        // ---- fix l = L-1: reference zero-pads the whole win row at t=L, so
        // ALL j=2 taps vanish there. Recompute with j in {0,1}. ----
        if (l0 + TL == LL) {
            float s = 0.0f;
            #pragma unroll
            for (int i = 0; i < 8; i++) {
                #pragma unroll
                for (int j = 0; j < 2; j++) {
                    s += ks[k * 24 + i * 3 + j] * rowA[TL + 20 + j - 3 * i];
                }
            }
            out[((size_t)(b * LL + LL - 1)) * NCOL + col] = s;
        }

        // ---- publish next tile into the other buffer ----
        if (hasnext) {
            int q = p ^ 1;
            int t0 = tid / CC, c0 = tid - t0 * CC;
            xsA[q][c0][t0] = n0;
            if (t0 >= 1) xsB[q][c0][t0 - 1] = n0;
            if (i1ok) {
                int i1 = tid + NCOL;
                int t1 = i1 / CC, c1 = i1 - t1 * CC;
                xsA[q][c1][t1] = n1;
                xsB[q][c1][t1 - 1] = n1;
            }
            __syncthreads();
            p = q;
        }
    }
}

extern "C" void kernel_launch(void* const* d_in, const int* in_sizes, int n_in,
                              void* d_out, int out_size) {
    const float* x    = (const float*)d_in[0];
    const float* kern = (const float*)d_in[1];
    float* out        = (float*)d_out;
    rocket_conv_kernel<<<GRID, NCOL>>>(x, kern, out);
}